// round 7
// baseline (speedup 1.0000x reference)
#include <cuda_runtime.h>

// ---------------------------------------------------------------------------
// BatchHetInfLinkPred: 2-layer MLP + 3 GAT layers (heads 4/2/1) on a graph
// N=50000 nodes, E=800000 edges (+N self loops). fp32 throughout.
//
// Strategy:
//   - Detect edge_index dtype on-device (int32 vs int64 layout).
//   - Build dst-CSR once per launch (count / scan / scatter) -> no float
//     atomics anywhere in the heavy path.
//   - Per GAT layer: tiled GEMM projection, per-node alpha dot products,
//     edge-parallel gather of alpha_src into CSR order, then one-warp-per-
//     dst-node softmax+aggregate fully in registers.
// ---------------------------------------------------------------------------

#define MAXN 50000
#define MAXE 800000
#define MAXET (MAXE + MAXN)

__device__ float g_h[MAXN * 128];      // 128-wide feature buffer
__device__ float g_f[MAXN * 256];      // 256-wide feature buffer
__device__ float g_proj[MAXN * 256];   // projection scratch
__device__ float g_as[MAXN * 4];       // alpha_src per node/head
__device__ float g_ad[MAXN * 4];       // alpha_dst per node/head
__device__ float g_e[(size_t)MAXET * 4]; // per-CSR-position gathered alpha_src
__device__ int   g_rowptr[MAXN + 1];
__device__ int   g_next[MAXN];         // counts -> running fill cursor
__device__ int   g_src[MAXET];         // CSR: src node per position
__device__ int   g_is64;               // edge_index dtype flag

// --------------------------- dtype detection -------------------------------
// int64 little-endian values < 2^31: every odd 32-bit word is 0.
// int32 random values in [0,N): essentially never 256 zeros in a row.

__global__ void k_detect(const unsigned int* __restrict__ w) {
    __shared__ int any;
    if (threadIdx.x == 0) any = 0;
    __syncthreads();
    if (w[2 * threadIdx.x + 1] != 0) any = 1;
    __syncthreads();
    if (threadIdx.x == 0) g_is64 = (any == 0) ? 1 : 0;
}

__device__ __forceinline__ void load_edge(const void* ei, int e, int i,
                                          int n, int& s, int& d, bool& ok) {
    if (i < e) {
        if (g_is64) {
            s = (int)((const long long*)ei)[i];
            d = (int)((const long long*)ei)[e + i];
        } else {
            s = ((const int*)ei)[i];
            d = ((const int*)ei)[e + i];
        }
    } else {
        s = d = i - e;
    }
    ok = ((unsigned)s < (unsigned)n) && ((unsigned)d < (unsigned)n);
}

// ------------------------------- CSR build --------------------------------

__global__ void k_zero_int(int n) {
    int i = blockIdx.x * blockDim.x + threadIdx.x;
    if (i < n) g_next[i] = 0;
}

__global__ void k_count(const void* __restrict__ ei, int e, int etot, int n) {
    int i = blockIdx.x * blockDim.x + threadIdx.x;
    if (i >= etot) return;
    int s, d; bool ok;
    load_edge(ei, e, i, n, s, d, ok);
    if (ok) atomicAdd(&g_next[d], 1);
}

// single-block inclusive-scan over counts -> exclusive row offsets
__global__ void k_scan(int n) {
    __shared__ int s[1024];
    __shared__ int carry_s;
    int t = threadIdx.x;
    if (t == 0) carry_s = 0;
    __syncthreads();
    for (int base = 0; base < n; base += 1024) {
        int v = (base + t < n) ? g_next[base + t] : 0;
        s[t] = v;
        __syncthreads();
        for (int off = 1; off < 1024; off <<= 1) {
            int add = (t >= off) ? s[t - off] : 0;
            __syncthreads();
            s[t] += add;
            __syncthreads();
        }
        int incl = s[t];
        int carry = carry_s;
        if (base + t < n) {
            int excl = carry + incl - v;
            g_rowptr[base + t] = excl;
            g_next[base + t] = excl;
        }
        __syncthreads();
        if (t == 1023) carry_s = carry + incl;
        __syncthreads();
    }
    if (t == 0) g_rowptr[n] = carry_s;
}

__global__ void k_scatter(const void* __restrict__ ei, int e, int etot, int n) {
    int i = blockIdx.x * blockDim.x + threadIdx.x;
    if (i >= etot) return;
    int s, d; bool ok;
    load_edge(ei, e, i, n, s, d, ok);
    if (!ok) return;
    int pos = atomicAdd(&g_next[d], 1);
    g_src[pos] = s;
}

// --------------------------------- GEMM -----------------------------------
// C[M,Ncol] = A[M,K] @ B[K,Ncol]; MODE 1: +bias then relu.
// BM=BN=64, BK=16, 256 threads, 4x4 per thread.

template <int MODE>
__global__ void k_gemm(const float* __restrict__ A, const float* __restrict__ B,
                       const float* __restrict__ bias, float* __restrict__ C,
                       int M, int K, int Ncol) {
    __shared__ float As[16][64];  // transposed: As[k][row]
    __shared__ float Bs[16][64];
    int tid = threadIdx.x;
    int tx = tid & 15, ty = tid >> 4;
    int row0 = blockIdx.y * 64;
    int col0 = blockIdx.x * 64;
    float acc[4][4] = {};

    int lr = tid >> 2;          // 0..63 : A tile row
    int lk = (tid & 3) * 4;     // 0,4,8,12 : A tile k offset
    int bkk = tid >> 4;         // 0..15 : B tile k
    int bc = (tid & 15) * 4;    // B tile col offset

    for (int k0 = 0; k0 < K; k0 += 16) {
        float4 av = make_float4(0.f, 0.f, 0.f, 0.f);
        int ar = row0 + lr;
        if (ar < M)
            av = *reinterpret_cast<const float4*>(&A[(size_t)ar * K + k0 + lk]);
        As[lk + 0][lr] = av.x; As[lk + 1][lr] = av.y;
        As[lk + 2][lr] = av.z; As[lk + 3][lr] = av.w;
        float4 bv = *reinterpret_cast<const float4*>(&B[(size_t)(k0 + bkk) * Ncol + col0 + bc]);
        *reinterpret_cast<float4*>(&Bs[bkk][bc]) = bv;
        __syncthreads();
#pragma unroll
        for (int kk = 0; kk < 16; kk++) {
            float a[4], b[4];
#pragma unroll
            for (int i = 0; i < 4; i++) a[i] = As[kk][ty + i * 16];
#pragma unroll
            for (int j = 0; j < 4; j++) b[j] = Bs[kk][tx + j * 16];
#pragma unroll
            for (int i = 0; i < 4; i++)
#pragma unroll
                for (int j = 0; j < 4; j++) acc[i][j] += a[i] * b[j];
        }
        __syncthreads();
    }
#pragma unroll
    for (int i = 0; i < 4; i++) {
        int r = row0 + ty + i * 16;
        if (r >= M) continue;
#pragma unroll
        for (int j = 0; j < 4; j++) {
            int c = col0 + tx + j * 16;
            float v = acc[i][j];
            if (MODE == 1) { v += bias[c]; v = fmaxf(v, 0.f); }
            C[(size_t)r * Ncol + c] = v;
        }
    }
}

// ------------------------- per-node alpha dot products ---------------------

template <int H, int C>
__global__ void k_alpha(const float* __restrict__ proj,
                        const float* __restrict__ a_s,
                        const float* __restrict__ a_d, int n) {
    const int HC = H * C, R = HC / 32;
    int warp = threadIdx.x >> 5, lane = threadIdx.x & 31;
    int node = blockIdx.x * 4 + warp;
    if (node >= n) return;
    float ps[H] = {}, pd[H] = {};
#pragma unroll
    for (int r = 0; r < R; r++) {
        const int h = (r * 32) / C;
        int ch = r * 32 + lane;
        float v = proj[(size_t)node * HC + ch];
        ps[h] += v * a_s[ch];
        pd[h] += v * a_d[ch];
    }
#pragma unroll
    for (int h = 0; h < H; h++) {
        float sv = ps[h], dv = pd[h];
#pragma unroll
        for (int off = 16; off; off >>= 1) {
            sv += __shfl_xor_sync(~0u, sv, off);
            dv += __shfl_xor_sync(~0u, dv, off);
        }
        if (lane == 0) { g_as[node * H + h] = sv; g_ad[node * H + h] = dv; }
    }
}

// -------- gather alpha_src into CSR position order (coalesced writes) ------

template <int H>
__global__ void k_gather(int etot) {
    int p = blockIdx.x * blockDim.x + threadIdx.x;
    if (p >= etot) return;
    int s = g_src[p];
    if (H == 4) {
        reinterpret_cast<float4*>(g_e)[p] = reinterpret_cast<const float4*>(g_as)[s];
    } else if (H == 2) {
        reinterpret_cast<float2*>(g_e)[p] = reinterpret_cast<const float2*>(g_as)[s];
    } else {
        g_e[p] = g_as[s];
    }
}

// ----------- warp-per-node softmax + message aggregation -------------------
// EPI 0: concat + bias + elu (gat1, H=4 C=64 -> out width 256)
// EPI 1: mean over 2 heads + bias + elu (gat2, H=2 C=128 -> out width 128)
// EPI 2: bias only (gat3, H=1 C=128 -> out width 128)

template <int H, int C, int EPI>
__global__ void k_agg(const float* __restrict__ proj,
                      const float* __restrict__ bias,
                      float* __restrict__ out, int n) {
    const int HC = H * C, R = HC / 32, EPW = 32 / H;
    __shared__ float sw[4][32];
    int warp = threadIdx.x >> 5, lane = threadIdx.x & 31;
    int node = blockIdx.x * 4 + warp;
    if (node >= n) return;

    float adh[H];
#pragma unroll
    for (int h = 0; h < H; h++) adh[h] = g_ad[node * H + h];

    int start = g_rowptr[node], end = g_rowptr[node + 1];
    int myh = lane & (H - 1);

    // pass 1: per-head max of leaky_relu(alpha_s[src] + alpha_d[dst])
    float m = -1e30f;
    for (int p = start + lane / H; p < end; p += EPW) {
        float e = g_e[(size_t)p * H + myh] + adh[myh];
        e = e > 0.f ? e : 0.2f * e;
        m = fmaxf(m, e);
    }
#pragma unroll
    for (int off = H; off < 32; off <<= 1) m = fmaxf(m, __shfl_xor_sync(~0u, m, off));
    // m is now the max for head (lane % H)

    // pass 2: fused exp / denom / weighted message accumulation
    float acc[R] = {};
    float den = 0.f;
    for (int cs = start; cs < end; cs += EPW) {
        int cnt = min(EPW, end - cs);
        int j = lane / H;
        float w = 0.f;
        if (j < cnt) {
            float e = g_e[(size_t)(cs + j) * H + myh] + adh[myh];
            e = e > 0.f ? e : 0.2f * e;
            w = __expf(e - m);
        }
        den += w;
        sw[warp][lane] = w;
        int ssrc = (lane < cnt) ? g_src[cs + lane] : 0;
        __syncwarp();
        for (int jj = 0; jj < cnt; jj++) {
            int src = __shfl_sync(~0u, ssrc, jj);
            const float* pr = proj + (size_t)src * HC;
#pragma unroll
            for (int r = 0; r < R; r++) {
                const int h = (r * 32) / C;
                acc[r] += sw[warp][jj * H + h] * pr[r * 32 + lane];
            }
        }
        __syncwarp();
    }
#pragma unroll
    for (int off = H; off < 32; off <<= 1) den += __shfl_xor_sync(~0u, den, off);
    float denh[H];
#pragma unroll
    for (int h = 0; h < H; h++) denh[h] = __shfl_sync(~0u, den, h) + 1e-16f;

    if (EPI == 0) {
#pragma unroll
        for (int r = 0; r < R; r++) {
            const int h = (r * 32) / C;
            int ch = r * 32 + lane;
            float v = acc[r] / denh[h] + bias[ch];
            v = v > 0.f ? v : (__expf(v) - 1.f);
            out[(size_t)node * HC + ch] = v;
        }
    } else if (EPI == 1) {
#pragma unroll
        for (int r = 0; r < 4; r++) {
            int ch = r * 32 + lane;
            float v = 0.5f * (acc[r] / denh[0] + acc[r + 4] / denh[H - 1]) + bias[ch];
            v = v > 0.f ? v : (__expf(v) - 1.f);
            out[(size_t)node * 128 + ch] = v;
        }
    } else {
#pragma unroll
        for (int r = 0; r < R; r++) {
            int ch = r * 32 + lane;
            float v = acc[r] / denh[0] + bias[ch];
            out[(size_t)node * C + ch] = v;
        }
    }
}

// ------------------------------- launch ------------------------------------

extern "C" void kernel_launch(void* const* d_in, const int* in_sizes, int n_in,
                              void* d_out, int out_size) {
    const float* x  = (const float*)d_in[0];
    const void*  ei = d_in[1];                 // int32 or int64 — detected on device
    const float* W1 = (const float*)d_in[2];
    const float* b1 = (const float*)d_in[3];
    const float* W2 = (const float*)d_in[4];
    const float* b2 = (const float*)d_in[5];
    const float* g1_W  = (const float*)d_in[6];
    const float* g1_as = (const float*)d_in[7];
    const float* g1_ad = (const float*)d_in[8];
    const float* g1_b  = (const float*)d_in[9];
    const float* g2_W  = (const float*)d_in[10];
    const float* g2_as = (const float*)d_in[11];
    const float* g2_ad = (const float*)d_in[12];
    const float* g2_b  = (const float*)d_in[13];
    const float* g3_W  = (const float*)d_in[14];
    const float* g3_as = (const float*)d_in[15];
    const float* g3_ad = (const float*)d_in[16];
    const float* g3_b  = (const float*)d_in[17];
    float* out = (float*)d_out;

    int n = in_sizes[0] / 256;      // IN = 256
    int e = in_sizes[1] / 2;
    int etot = e + n;

    // device pointers to __device__ globals (for GEMM args)
    float *d_h, *d_f, *d_proj;
    cudaGetSymbolAddress((void**)&d_h, g_h);
    cudaGetSymbolAddress((void**)&d_f, g_f);
    cudaGetSymbolAddress((void**)&d_proj, g_proj);

    int nb = (n + 3) / 4;

    // --- dtype detect + CSR build ---
    k_detect<<<1, 256>>>((const unsigned int*)ei);
    k_zero_int<<<(n + 255) / 256, 256>>>(n);
    k_count<<<(etot + 255) / 256, 256>>>(ei, e, etot, n);
    k_scan<<<1, 1024>>>(n);
    k_scatter<<<(etot + 255) / 256, 256>>>(ei, e, etot, n);

    // --- semantic MLP ---
    k_gemm<1><<<dim3(2, (n + 63) / 64), 256>>>(x, W1, b1, d_f, n, 256, 128);
    k_gemm<1><<<dim3(2, (n + 63) / 64), 256>>>(d_f, W2, b2, d_h, n, 128, 128);

    // --- GAT1: HID(128) -> 4 heads x 64, concat -> 256, ELU ---
    k_gemm<0><<<dim3(4, (n + 63) / 64), 256>>>(d_h, g1_W, nullptr, d_proj, n, 128, 256);
    k_alpha<4, 64><<<nb, 128>>>(d_proj, g1_as, g1_ad, n);
    k_gather<4><<<(etot + 255) / 256, 256>>>(etot);
    k_agg<4, 64, 0><<<nb, 128>>>(d_proj, g1_b, d_f, n);

    // --- GAT2: 256 -> 2 heads x 128, mean -> 128, ELU ---
    k_gemm<0><<<dim3(4, (n + 63) / 64), 256>>>(d_f, g2_W, nullptr, d_proj, n, 256, 256);
    k_alpha<2, 128><<<nb, 128>>>(d_proj, g2_as, g2_ad, n);
    k_gather<2><<<(etot + 255) / 256, 256>>>(etot);
    k_agg<2, 128, 1><<<nb, 128>>>(d_proj, g2_b, d_h, n);

    // --- GAT3: 128 -> 1 head x 128, mean(=id) -> 128 ---
    k_gemm<0><<<dim3(2, (n + 63) / 64), 256>>>(d_h, g3_W, nullptr, d_proj, n, 128, 128);
    k_alpha<1, 128><<<nb, 128>>>(d_proj, g3_as, g3_ad, n);
    k_gather<1><<<(etot + 255) / 256, 256>>>(etot);
    k_agg<1, 128, 2><<<nb, 128>>>(d_proj, g3_b, out, n);
}

// round 8
// speedup vs baseline: 1.4310x; 1.4310x over previous
#include <cuda_runtime.h>

// ---------------------------------------------------------------------------
// BatchHetInfLinkPred: 2-layer MLP + 3 GAT layers (heads 4/2/1).
// N=50000 nodes, E=800000 edges (+N self loops).
//
// Round 8: multi-block CSR scan (was 83us single-block) + TF32 tensor-core
// GEMM with 3xTF32 compensation (fp32 SIMT was pinned at the ~34TF/s fma
// ceiling; tensor pipe was idle).
// ---------------------------------------------------------------------------

#define MAXN 50000
#define MAXE 800000
#define MAXET (MAXE + MAXN)

__device__ float g_h[MAXN * 128];
__device__ float g_f[MAXN * 256];
__device__ float g_proj[MAXN * 256];
__device__ float g_as[MAXN * 4];
__device__ float g_ad[MAXN * 4];
__device__ float g_e[(size_t)MAXET * 4];
__device__ int   g_rowptr[MAXN + 1];
__device__ int   g_next[MAXN];
__device__ int   g_src[MAXET];
__device__ int   g_is64;
__device__ int   g_bsum[64];

// --------------------------- dtype detection -------------------------------

__global__ void k_detect(const unsigned int* __restrict__ w) {
    __shared__ int any;
    if (threadIdx.x == 0) any = 0;
    __syncthreads();
    if (w[2 * threadIdx.x + 1] != 0) any = 1;
    __syncthreads();
    if (threadIdx.x == 0) g_is64 = (any == 0) ? 1 : 0;
}

__device__ __forceinline__ void load_edge(const void* ei, int e, int i,
                                          int n, int& s, int& d, bool& ok) {
    if (i < e) {
        if (g_is64) {
            s = (int)((const long long*)ei)[i];
            d = (int)((const long long*)ei)[e + i];
        } else {
            s = ((const int*)ei)[i];
            d = ((const int*)ei)[e + i];
        }
    } else {
        s = d = i - e;
    }
    ok = ((unsigned)s < (unsigned)n) && ((unsigned)d < (unsigned)n);
}

// ------------------------------- CSR build --------------------------------

__global__ void k_zero_int(int n) {
    int i = blockIdx.x * blockDim.x + threadIdx.x;
    if (i < n) g_next[i] = 0;
}

__global__ void k_count(const void* __restrict__ ei, int e, int etot, int n) {
    int i = blockIdx.x * blockDim.x + threadIdx.x;
    if (i >= etot) return;
    int s, d; bool ok;
    load_edge(ei, e, i, n, s, d, ok);
    if (ok) atomicAdd(&g_next[d], 1);
}

// multi-block scan: per-block exclusive scan + block sums
__global__ void k_scan1(int n) {
    __shared__ int s[1024];
    int t = threadIdx.x;
    int gi = blockIdx.x * 1024 + t;
    int v = (gi < n) ? g_next[gi] : 0;
    s[t] = v;
    __syncthreads();
    for (int off = 1; off < 1024; off <<= 1) {
        int add = (t >= off) ? s[t - off] : 0;
        __syncthreads();
        s[t] += add;
        __syncthreads();
    }
    if (gi < n) g_rowptr[gi] = s[t] - v;   // block-local exclusive
    if (t == 1023) g_bsum[blockIdx.x] = s[1023];
}

// scan the (<=64) block sums
__global__ void k_scan2(int nb, int n) {
    __shared__ int s[64];
    int t = threadIdx.x;
    int v = (t < nb) ? g_bsum[t] : 0;
    s[t] = v;
    __syncthreads();
    for (int off = 1; off < 64; off <<= 1) {
        int add = (t >= off) ? s[t - off] : 0;
        __syncthreads();
        s[t] += add;
        __syncthreads();
    }
    if (t < nb) g_bsum[t] = s[t] - v;      // exclusive block offsets
    if (t == 63) g_rowptr[n] = s[63];      // grand total
}

__global__ void k_scan3(int n) {
    int gi = blockIdx.x * 1024 + threadIdx.x;
    if (gi < n) {
        int v = g_rowptr[gi] + g_bsum[blockIdx.x];
        g_rowptr[gi] = v;
        g_next[gi] = v;
    }
}

__global__ void k_scatter(const void* __restrict__ ei, int e, int etot, int n) {
    int i = blockIdx.x * blockDim.x + threadIdx.x;
    if (i >= etot) return;
    int s, d; bool ok;
    load_edge(ei, e, i, n, s, d, ok);
    if (!ok) return;
    int pos = atomicAdd(&g_next[d], 1);
    g_src[pos] = s;
}

// ----------------------- TF32 tensor-core GEMM -----------------------------
// C[M,Ncol] = A[M,K] @ B[K,Ncol], 3xTF32 compensation (near-fp32 accuracy).
// Block tile 128x64, 8 warps in 4x2, warp tile 32x32 = 2x4 m16n8k8 tiles.
// MODE 1: +bias then relu.

__device__ __forceinline__ unsigned f2tf32(float x) {
    unsigned r;
    asm("cvt.rna.tf32.f32 %0, %1;" : "=r"(r) : "f"(x));
    return r;
}
__device__ __forceinline__ void split_tf32(float v, unsigned& h, unsigned& l) {
    h = f2tf32(v);
    l = f2tf32(v - __uint_as_float(h));
}
__device__ __forceinline__ void mma8(float* c, const unsigned* a, const unsigned* b) {
    asm volatile(
        "mma.sync.aligned.m16n8k8.row.col.f32.tf32.tf32.f32 "
        "{%0,%1,%2,%3},{%4,%5,%6,%7},{%8,%9},{%0,%1,%2,%3};"
        : "+f"(c[0]), "+f"(c[1]), "+f"(c[2]), "+f"(c[3])
        : "r"(a[0]), "r"(a[1]), "r"(a[2]), "r"(a[3]), "r"(b[0]), "r"(b[1]));
}

template <int MODE>
__global__ __launch_bounds__(256) void k_gemm(
    const float* __restrict__ A, const float* __restrict__ B,
    const float* __restrict__ bias, float* __restrict__ C,
    int M, int K, int Ncol) {
    __shared__ float As[128][36];   // [m][k], pad 36 -> conflict-free frag reads
    __shared__ float Bs[32][68];    // [k][n], pad 68
    int tid = threadIdx.x, lane = tid & 31, warp = tid >> 5;
    int g = lane >> 2, t = lane & 3;
    int wm = (warp >> 1) * 32, wn = (warp & 1) * 32;
    int row0 = blockIdx.y * 128, col0 = blockIdx.x * 64;
    float acc[2][4][4] = {};

    for (int k0 = 0; k0 < K; k0 += 32) {
        // A tile: 128x32 floats = 1024 float4, 4 per thread (clamp rows)
#pragma unroll
        for (int u = 0; u < 4; u++) {
            int fi = tid + u * 256;
            int r = fi >> 3, kq = (fi & 7) * 4;
            int ar = min(row0 + r, M - 1);
            float4 av = *reinterpret_cast<const float4*>(&A[(size_t)ar * K + k0 + kq]);
            *reinterpret_cast<float4*>(&As[r][kq]) = av;
        }
        // B tile: 32x64 floats = 512 float4, 2 per thread
#pragma unroll
        for (int u = 0; u < 2; u++) {
            int fi = tid + u * 256;
            int bk = fi >> 4, bn = (fi & 15) * 4;
            float4 bv = *reinterpret_cast<const float4*>(&B[(size_t)(k0 + bk) * Ncol + col0 + bn]);
            *reinterpret_cast<float4*>(&Bs[bk][bn]) = bv;
        }
        __syncthreads();
#pragma unroll
        for (int ks = 0; ks < 32; ks += 8) {
            unsigned ah[2][4], al[2][4], bh[4][2], bl[4][2];
#pragma unroll
            for (int i = 0; i < 2; i++) {
                int r = wm + i * 16;
                split_tf32(As[r + g][ks + t],         ah[i][0], al[i][0]);
                split_tf32(As[r + g + 8][ks + t],     ah[i][1], al[i][1]);
                split_tf32(As[r + g][ks + t + 4],     ah[i][2], al[i][2]);
                split_tf32(As[r + g + 8][ks + t + 4], ah[i][3], al[i][3]);
            }
#pragma unroll
            for (int j = 0; j < 4; j++) {
                int c = wn + j * 8;
                split_tf32(Bs[ks + t][c + g],     bh[j][0], bl[j][0]);
                split_tf32(Bs[ks + t + 4][c + g], bh[j][1], bl[j][1]);
            }
#pragma unroll
            for (int i = 0; i < 2; i++)
#pragma unroll
                for (int j = 0; j < 4; j++) {
                    mma8(acc[i][j], ah[i], bh[j]);
                    mma8(acc[i][j], ah[i], bl[j]);
                    mma8(acc[i][j], al[i], bh[j]);
                }
        }
        __syncthreads();
    }
    // epilogue: c0 (g,2t) c1 (g,2t+1) c2 (g+8,2t) c3 (g+8,2t+1)
#pragma unroll
    for (int i = 0; i < 2; i++) {
        int r0 = row0 + wm + i * 16 + g;
#pragma unroll
        for (int j = 0; j < 4; j++) {
            int c = col0 + wn + j * 8 + t * 2;
            float v0 = acc[i][j][0], v1 = acc[i][j][1];
            float v2 = acc[i][j][2], v3 = acc[i][j][3];
            if (MODE == 1) {
                v0 = fmaxf(v0 + bias[c], 0.f);     v1 = fmaxf(v1 + bias[c + 1], 0.f);
                v2 = fmaxf(v2 + bias[c], 0.f);     v3 = fmaxf(v3 + bias[c + 1], 0.f);
            }
            if (r0 < M) {
                C[(size_t)r0 * Ncol + c] = v0;
                C[(size_t)r0 * Ncol + c + 1] = v1;
            }
            if (r0 + 8 < M) {
                C[(size_t)(r0 + 8) * Ncol + c] = v2;
                C[(size_t)(r0 + 8) * Ncol + c + 1] = v3;
            }
        }
    }
}

// ------------------------- per-node alpha dot products ---------------------

template <int H, int C>
__global__ void k_alpha(const float* __restrict__ proj,
                        const float* __restrict__ a_s,
                        const float* __restrict__ a_d, int n) {
    const int HC = H * C, R = HC / 32;
    int warp = threadIdx.x >> 5, lane = threadIdx.x & 31;
    int node = blockIdx.x * 4 + warp;
    if (node >= n) return;
    float ps[H] = {}, pd[H] = {};
#pragma unroll
    for (int r = 0; r < R; r++) {
        const int h = (r * 32) / C;
        int ch = r * 32 + lane;
        float v = proj[(size_t)node * HC + ch];
        ps[h] += v * a_s[ch];
        pd[h] += v * a_d[ch];
    }
#pragma unroll
    for (int h = 0; h < H; h++) {
        float sv = ps[h], dv = pd[h];
#pragma unroll
        for (int off = 16; off; off >>= 1) {
            sv += __shfl_xor_sync(~0u, sv, off);
            dv += __shfl_xor_sync(~0u, dv, off);
        }
        if (lane == 0) { g_as[node * H + h] = sv; g_ad[node * H + h] = dv; }
    }
}

// -------- gather alpha_src into CSR position order -------------------------

template <int H>
__global__ void k_gather(int etot) {
    int p = blockIdx.x * blockDim.x + threadIdx.x;
    if (p >= etot) return;
    int s = g_src[p];
    if (H == 4) {
        reinterpret_cast<float4*>(g_e)[p] = reinterpret_cast<const float4*>(g_as)[s];
    } else if (H == 2) {
        reinterpret_cast<float2*>(g_e)[p] = reinterpret_cast<const float2*>(g_as)[s];
    } else {
        g_e[p] = g_as[s];
    }
}

// ----------- warp-per-node softmax + message aggregation -------------------

template <int H, int C, int EPI>
__global__ void k_agg(const float* __restrict__ proj,
                      const float* __restrict__ bias,
                      float* __restrict__ out, int n) {
    const int HC = H * C, R = HC / 32, EPW = 32 / H;
    __shared__ float sw[4][32];
    int warp = threadIdx.x >> 5, lane = threadIdx.x & 31;
    int node = blockIdx.x * 4 + warp;
    if (node >= n) return;

    float adh[H];
#pragma unroll
    for (int h = 0; h < H; h++) adh[h] = g_ad[node * H + h];

    int start = g_rowptr[node], end = g_rowptr[node + 1];
    int myh = lane & (H - 1);

    float m = -1e30f;
    for (int p = start + lane / H; p < end; p += EPW) {
        float e = g_e[(size_t)p * H + myh] + adh[myh];
        e = e > 0.f ? e : 0.2f * e;
        m = fmaxf(m, e);
    }
#pragma unroll
    for (int off = H; off < 32; off <<= 1) m = fmaxf(m, __shfl_xor_sync(~0u, m, off));

    float acc[R] = {};
    float den = 0.f;
    for (int cs = start; cs < end; cs += EPW) {
        int cnt = min(EPW, end - cs);
        int j = lane / H;
        float w = 0.f;
        if (j < cnt) {
            float e = g_e[(size_t)(cs + j) * H + myh] + adh[myh];
            e = e > 0.f ? e : 0.2f * e;
            w = __expf(e - m);
        }
        den += w;
        sw[warp][lane] = w;
        int ssrc = (lane < cnt) ? g_src[cs + lane] : 0;
        __syncwarp();
        for (int jj = 0; jj < cnt; jj++) {
            int src = __shfl_sync(~0u, ssrc, jj);
            const float* pr = proj + (size_t)src * HC;
#pragma unroll
            for (int r = 0; r < R; r++) {
                const int h = (r * 32) / C;
                acc[r] += sw[warp][jj * H + h] * pr[r * 32 + lane];
            }
        }
        __syncwarp();
    }
#pragma unroll
    for (int off = H; off < 32; off <<= 1) den += __shfl_xor_sync(~0u, den, off);
    float denh[H];
#pragma unroll
    for (int h = 0; h < H; h++) denh[h] = __shfl_sync(~0u, den, h) + 1e-16f;

    if (EPI == 0) {
#pragma unroll
        for (int r = 0; r < R; r++) {
            const int h = (r * 32) / C;
            int ch = r * 32 + lane;
            float v = acc[r] / denh[h] + bias[ch];
            v = v > 0.f ? v : (__expf(v) - 1.f);
            out[(size_t)node * HC + ch] = v;
        }
    } else if (EPI == 1) {
#pragma unroll
        for (int r = 0; r < 4; r++) {
            int ch = r * 32 + lane;
            float v = 0.5f * (acc[r] / denh[0] + acc[r + 4] / denh[H - 1]) + bias[ch];
            v = v > 0.f ? v : (__expf(v) - 1.f);
            out[(size_t)node * 128 + ch] = v;
        }
    } else {
#pragma unroll
        for (int r = 0; r < R; r++) {
            int ch = r * 32 + lane;
            float v = acc[r] / denh[0] + bias[ch];
            out[(size_t)node * C + ch] = v;
        }
    }
}

// ------------------------------- launch ------------------------------------

extern "C" void kernel_launch(void* const* d_in, const int* in_sizes, int n_in,
                              void* d_out, int out_size) {
    const float* x  = (const float*)d_in[0];
    const void*  ei = d_in[1];
    const float* W1 = (const float*)d_in[2];
    const float* b1 = (const float*)d_in[3];
    const float* W2 = (const float*)d_in[4];
    const float* b2 = (const float*)d_in[5];
    const float* g1_W  = (const float*)d_in[6];
    const float* g1_as = (const float*)d_in[7];
    const float* g1_ad = (const float*)d_in[8];
    const float* g1_b  = (const float*)d_in[9];
    const float* g2_W  = (const float*)d_in[10];
    const float* g2_as = (const float*)d_in[11];
    const float* g2_ad = (const float*)d_in[12];
    const float* g2_b  = (const float*)d_in[13];
    const float* g3_W  = (const float*)d_in[14];
    const float* g3_as = (const float*)d_in[15];
    const float* g3_ad = (const float*)d_in[16];
    const float* g3_b  = (const float*)d_in[17];
    float* out = (float*)d_out;

    int n = in_sizes[0] / 256;
    int e = in_sizes[1] / 2;
    int etot = e + n;

    float *d_h, *d_f, *d_proj;
    cudaGetSymbolAddress((void**)&d_h, g_h);
    cudaGetSymbolAddress((void**)&d_f, g_f);
    cudaGetSymbolAddress((void**)&d_proj, g_proj);

    int nb = (n + 3) / 4;
    int nsb = (n + 1023) / 1024;
    int gy = (n + 127) / 128;

    // --- dtype detect + CSR build ---
    k_detect<<<1, 256>>>((const unsigned int*)ei);
    k_zero_int<<<(n + 255) / 256, 256>>>(n);
    k_count<<<(etot + 255) / 256, 256>>>(ei, e, etot, n);
    k_scan1<<<nsb, 1024>>>(n);
    k_scan2<<<1, 64>>>(nsb, n);
    k_scan3<<<nsb, 1024>>>(n);
    k_scatter<<<(etot + 255) / 256, 256>>>(ei, e, etot, n);

    // --- semantic MLP ---
    k_gemm<1><<<dim3(2, gy), 256>>>(x, W1, b1, d_f, n, 256, 128);
    k_gemm<1><<<dim3(2, gy), 256>>>(d_f, W2, b2, d_h, n, 128, 128);

    // --- GAT1: 128 -> 4 heads x 64, concat -> 256, ELU ---
    k_gemm<0><<<dim3(4, gy), 256>>>(d_h, g1_W, nullptr, d_proj, n, 128, 256);
    k_alpha<4, 64><<<nb, 128>>>(d_proj, g1_as, g1_ad, n);
    k_gather<4><<<(etot + 255) / 256, 256>>>(etot);
    k_agg<4, 64, 0><<<nb, 128>>>(d_proj, g1_b, d_f, n);

    // --- GAT2: 256 -> 2 heads x 128, mean -> 128, ELU ---
    k_gemm<0><<<dim3(4, gy), 256>>>(d_f, g2_W, nullptr, d_proj, n, 256, 256);
    k_alpha<2, 128><<<nb, 128>>>(d_proj, g2_as, g2_ad, n);
    k_gather<2><<<(etot + 255) / 256, 256>>>(etot);
    k_agg<2, 128, 1><<<nb, 128>>>(d_proj, g2_b, d_h, n);

    // --- GAT3: 128 -> 1 head x 128, mean(=id) -> 128 ---
    k_gemm<0><<<dim3(2, gy), 256>>>(d_h, g3_W, nullptr, d_proj, n, 128, 128);
    k_alpha<1, 128><<<nb, 128>>>(d_proj, g3_as, g3_ad, n);
    k_gather<1><<<(etot + 255) / 256, 256>>>(etot);
    k_agg<1, 128, 2><<<nb, 128>>>(d_proj, g3_b, out, n);
}

// round 9
// speedup vs baseline: 1.4699x; 1.0272x over previous
#include <cuda_runtime.h>

// ---------------------------------------------------------------------------
// BatchHetInfLinkPred: 2-layer MLP + 3 GAT layers (heads 4/2/1).
// N=50000 nodes, E=800000 edges (+N self loops).
//
// Round 9: k_agg aggregation loop vectorized to float4 LDG.128 + shfl-based
// weight broadcast (removes smem staging + syncwarp). k_alpha vectorized.
// ---------------------------------------------------------------------------

#define MAXN 50000
#define MAXE 800000
#define MAXET (MAXE + MAXN)

__device__ float g_h[MAXN * 128];
__device__ float g_f[MAXN * 256];
__device__ float g_proj[MAXN * 256];
__device__ float g_as[MAXN * 4];
__device__ float g_ad[MAXN * 4];
__device__ float g_e[(size_t)MAXET * 4];
__device__ int   g_rowptr[MAXN + 1];
__device__ int   g_next[MAXN];
__device__ int   g_src[MAXET];
__device__ int   g_is64;
__device__ int   g_bsum[64];

// --------------------------- dtype detection -------------------------------

__global__ void k_detect(const unsigned int* __restrict__ w) {
    __shared__ int any;
    if (threadIdx.x == 0) any = 0;
    __syncthreads();
    if (w[2 * threadIdx.x + 1] != 0) any = 1;
    __syncthreads();
    if (threadIdx.x == 0) g_is64 = (any == 0) ? 1 : 0;
}

__device__ __forceinline__ void load_edge(const void* ei, int e, int i,
                                          int n, int& s, int& d, bool& ok) {
    if (i < e) {
        if (g_is64) {
            s = (int)((const long long*)ei)[i];
            d = (int)((const long long*)ei)[e + i];
        } else {
            s = ((const int*)ei)[i];
            d = ((const int*)ei)[e + i];
        }
    } else {
        s = d = i - e;
    }
    ok = ((unsigned)s < (unsigned)n) && ((unsigned)d < (unsigned)n);
}

// ------------------------------- CSR build --------------------------------

__global__ void k_zero_int(int n) {
    int i = blockIdx.x * blockDim.x + threadIdx.x;
    if (i < n) g_next[i] = 0;
}

__global__ void k_count(const void* __restrict__ ei, int e, int etot, int n) {
    int i = blockIdx.x * blockDim.x + threadIdx.x;
    if (i >= etot) return;
    int s, d; bool ok;
    load_edge(ei, e, i, n, s, d, ok);
    if (ok) atomicAdd(&g_next[d], 1);
}

__global__ void k_scan1(int n) {
    __shared__ int s[1024];
    int t = threadIdx.x;
    int gi = blockIdx.x * 1024 + t;
    int v = (gi < n) ? g_next[gi] : 0;
    s[t] = v;
    __syncthreads();
    for (int off = 1; off < 1024; off <<= 1) {
        int add = (t >= off) ? s[t - off] : 0;
        __syncthreads();
        s[t] += add;
        __syncthreads();
    }
    if (gi < n) g_rowptr[gi] = s[t] - v;
    if (t == 1023) g_bsum[blockIdx.x] = s[1023];
}

__global__ void k_scan2(int nb, int n) {
    __shared__ int s[64];
    int t = threadIdx.x;
    int v = (t < nb) ? g_bsum[t] : 0;
    s[t] = v;
    __syncthreads();
    for (int off = 1; off < 64; off <<= 1) {
        int add = (t >= off) ? s[t - off] : 0;
        __syncthreads();
        s[t] += add;
        __syncthreads();
    }
    if (t < nb) g_bsum[t] = s[t] - v;
    if (t == 63) g_rowptr[n] = s[63];
}

__global__ void k_scan3(int n) {
    int gi = blockIdx.x * 1024 + threadIdx.x;
    if (gi < n) {
        int v = g_rowptr[gi] + g_bsum[blockIdx.x];
        g_rowptr[gi] = v;
        g_next[gi] = v;
    }
}

__global__ void k_scatter(const void* __restrict__ ei, int e, int etot, int n) {
    int i = blockIdx.x * blockDim.x + threadIdx.x;
    if (i >= etot) return;
    int s, d; bool ok;
    load_edge(ei, e, i, n, s, d, ok);
    if (!ok) return;
    int pos = atomicAdd(&g_next[d], 1);
    g_src[pos] = s;
}

// ----------------------- TF32 tensor-core GEMM -----------------------------

__device__ __forceinline__ unsigned f2tf32(float x) {
    unsigned r;
    asm("cvt.rna.tf32.f32 %0, %1;" : "=r"(r) : "f"(x));
    return r;
}
__device__ __forceinline__ void split_tf32(float v, unsigned& h, unsigned& l) {
    h = f2tf32(v);
    l = f2tf32(v - __uint_as_float(h));
}
__device__ __forceinline__ void mma8(float* c, const unsigned* a, const unsigned* b) {
    asm volatile(
        "mma.sync.aligned.m16n8k8.row.col.f32.tf32.tf32.f32 "
        "{%0,%1,%2,%3},{%4,%5,%6,%7},{%8,%9},{%0,%1,%2,%3};"
        : "+f"(c[0]), "+f"(c[1]), "+f"(c[2]), "+f"(c[3])
        : "r"(a[0]), "r"(a[1]), "r"(a[2]), "r"(a[3]), "r"(b[0]), "r"(b[1]));
}

template <int MODE>
__global__ __launch_bounds__(256) void k_gemm(
    const float* __restrict__ A, const float* __restrict__ B,
    const float* __restrict__ bias, float* __restrict__ C,
    int M, int K, int Ncol) {
    __shared__ float As[128][36];
    __shared__ float Bs[32][68];
    int tid = threadIdx.x, lane = tid & 31, warp = tid >> 5;
    int g = lane >> 2, t = lane & 3;
    int wm = (warp >> 1) * 32, wn = (warp & 1) * 32;
    int row0 = blockIdx.y * 128, col0 = blockIdx.x * 64;
    float acc[2][4][4] = {};

    for (int k0 = 0; k0 < K; k0 += 32) {
#pragma unroll
        for (int u = 0; u < 4; u++) {
            int fi = tid + u * 256;
            int r = fi >> 3, kq = (fi & 7) * 4;
            int ar = min(row0 + r, M - 1);
            float4 av = *reinterpret_cast<const float4*>(&A[(size_t)ar * K + k0 + kq]);
            *reinterpret_cast<float4*>(&As[r][kq]) = av;
        }
#pragma unroll
        for (int u = 0; u < 2; u++) {
            int fi = tid + u * 256;
            int bk = fi >> 4, bn = (fi & 15) * 4;
            float4 bv = *reinterpret_cast<const float4*>(&B[(size_t)(k0 + bk) * Ncol + col0 + bn]);
            *reinterpret_cast<float4*>(&Bs[bk][bn]) = bv;
        }
        __syncthreads();
#pragma unroll
        for (int ks = 0; ks < 32; ks += 8) {
            unsigned ah[2][4], al[2][4], bh[4][2], bl[4][2];
#pragma unroll
            for (int i = 0; i < 2; i++) {
                int r = wm + i * 16;
                split_tf32(As[r + g][ks + t],         ah[i][0], al[i][0]);
                split_tf32(As[r + g + 8][ks + t],     ah[i][1], al[i][1]);
                split_tf32(As[r + g][ks + t + 4],     ah[i][2], al[i][2]);
                split_tf32(As[r + g + 8][ks + t + 4], ah[i][3], al[i][3]);
            }
#pragma unroll
            for (int j = 0; j < 4; j++) {
                int c = wn + j * 8;
                split_tf32(Bs[ks + t][c + g],     bh[j][0], bl[j][0]);
                split_tf32(Bs[ks + t + 4][c + g], bh[j][1], bl[j][1]);
            }
#pragma unroll
            for (int i = 0; i < 2; i++)
#pragma unroll
                for (int j = 0; j < 4; j++) {
                    mma8(acc[i][j], ah[i], bh[j]);
                    mma8(acc[i][j], ah[i], bl[j]);
                    mma8(acc[i][j], al[i], bh[j]);
                }
        }
        __syncthreads();
    }
#pragma unroll
    for (int i = 0; i < 2; i++) {
        int r0 = row0 + wm + i * 16 + g;
#pragma unroll
        for (int j = 0; j < 4; j++) {
            int c = col0 + wn + j * 8 + t * 2;
            float v0 = acc[i][j][0], v1 = acc[i][j][1];
            float v2 = acc[i][j][2], v3 = acc[i][j][3];
            if (MODE == 1) {
                v0 = fmaxf(v0 + bias[c], 0.f);     v1 = fmaxf(v1 + bias[c + 1], 0.f);
                v2 = fmaxf(v2 + bias[c], 0.f);     v3 = fmaxf(v3 + bias[c + 1], 0.f);
            }
            if (r0 < M) {
                C[(size_t)r0 * Ncol + c] = v0;
                C[(size_t)r0 * Ncol + c + 1] = v1;
            }
            if (r0 + 8 < M) {
                C[(size_t)(r0 + 8) * Ncol + c] = v2;
                C[(size_t)(r0 + 8) * Ncol + c + 1] = v3;
            }
        }
    }
}

// ------------------------- per-node alpha dot products ---------------------
// float4 per lane: lane covers channels 4*lane + 128*q.

template <int H, int C>
__global__ void k_alpha(const float* __restrict__ proj,
                        const float* __restrict__ a_s,
                        const float* __restrict__ a_d, int n) {
    const int HC = H * C, Q = HC / 128;
    int warp = threadIdx.x >> 5, lane = threadIdx.x & 31;
    int node = blockIdx.x * 4 + warp;
    if (node >= n) return;
    float ps[H] = {}, pd[H] = {};
    const float4* pr = reinterpret_cast<const float4*>(proj + (size_t)node * HC);
    const float4* asv = reinterpret_cast<const float4*>(a_s);
    const float4* adv = reinterpret_cast<const float4*>(a_d);
#pragma unroll
    for (int q = 0; q < Q; q++) {
        const int h = (q * 128) / C + ((C == 64) ? 0 : 0); // base head of this q
        int idx = q * 32 + lane;
        int hh = (idx * 4) / C;
        float4 v = pr[idx];
        float4 as4 = asv[idx];
        float4 ad4 = adv[idx];
        float s = v.x * as4.x + v.y * as4.y + v.z * as4.z + v.w * as4.w;
        float d = v.x * ad4.x + v.y * ad4.y + v.z * ad4.z + v.w * ad4.w;
        // accumulate into head hh (runtime index but small H)
#pragma unroll
        for (int h2 = 0; h2 < H; h2++) {
            if (h2 == hh) { ps[h2] += s; pd[h2] += d; }
        }
        (void)h;
    }
#pragma unroll
    for (int h = 0; h < H; h++) {
        float sv = ps[h], dv = pd[h];
#pragma unroll
        for (int off = 16; off; off >>= 1) {
            sv += __shfl_xor_sync(~0u, sv, off);
            dv += __shfl_xor_sync(~0u, dv, off);
        }
        if (lane == 0) { g_as[node * H + h] = sv; g_ad[node * H + h] = dv; }
    }
}

// -------- gather alpha_src into CSR position order -------------------------

template <int H>
__global__ void k_gather(int etot) {
    int p = blockIdx.x * blockDim.x + threadIdx.x;
    if (p >= etot) return;
    int s = g_src[p];
    if (H == 4) {
        reinterpret_cast<float4*>(g_e)[p] = reinterpret_cast<const float4*>(g_as)[s];
    } else if (H == 2) {
        reinterpret_cast<float2*>(g_e)[p] = reinterpret_cast<const float2*>(g_as)[s];
    } else {
        g_e[p] = g_as[s];
    }
}

// ----------- warp-per-node softmax + message aggregation -------------------
// float4 gathers + shfl weight broadcast; no smem, no syncwarp.
// EPI 0: concat + bias + elu (gat1, H=4 C=64 -> 256 wide)
// EPI 1: mean over 2 heads + bias + elu (gat2, H=2 C=128 -> 128 wide)
// EPI 2: bias only (gat3, H=1 C=128 -> 128 wide)

template <int H, int C, int EPI>
__global__ __launch_bounds__(128) void k_agg(
    const float* __restrict__ proj, const float* __restrict__ bias,
    float* __restrict__ out, int n) {
    const int HC = H * C, Q = HC / 128, EPW = 32 / H;
    int warp = threadIdx.x >> 5, lane = threadIdx.x & 31;
    int node = blockIdx.x * 4 + warp;
    if (node >= n) return;

    float adh[H];
#pragma unroll
    for (int h = 0; h < H; h++) adh[h] = g_ad[node * H + h];

    int start = g_rowptr[node], end = g_rowptr[node + 1];
    int myh = lane & (H - 1);

    // pass 1: per-head max (head of lane = lane % H)
    float m = -1e30f;
    for (int p = start + lane / H; p < end; p += EPW) {
        float e = g_e[(size_t)p * H + myh] + adh[myh];
        e = e > 0.f ? e : 0.2f * e;
        m = fmaxf(m, e);
    }
#pragma unroll
    for (int off = H; off < 32; off <<= 1) m = fmaxf(m, __shfl_xor_sync(~0u, m, off));

    // head index of each q-th float4 load for this lane
    int hq[Q];
#pragma unroll
    for (int q = 0; q < Q; q++) hq[q] = (q * 128 + lane * 4) / C;

    // pass 2: fused exp / denom / weighted float4 aggregation
    float4 acc4[Q];
#pragma unroll
    for (int q = 0; q < Q; q++) acc4[q] = make_float4(0.f, 0.f, 0.f, 0.f);
    float den = 0.f;

    for (int cs = start; cs < end; cs += EPW) {
        int cnt = min(EPW, end - cs);
        int j = lane / H;
        float w = 0.f;
        if (j < cnt) {
            float e = g_e[(size_t)(cs + j) * H + myh] + adh[myh];
            e = e > 0.f ? e : 0.2f * e;
            w = __expf(e - m);
        }
        den += w;
        int ssrc = (lane < cnt) ? g_src[cs + lane] : 0;
        for (int jj = 0; jj < cnt; jj++) {
            int src = __shfl_sync(~0u, ssrc, jj);
            const float4* pr = reinterpret_cast<const float4*>(proj + (size_t)src * HC);
#pragma unroll
            for (int q = 0; q < Q; q++) {
                float wq = __shfl_sync(~0u, w, jj * H + hq[q]);
                float4 p = pr[q * 32 + lane];
                acc4[q].x += wq * p.x;
                acc4[q].y += wq * p.y;
                acc4[q].z += wq * p.z;
                acc4[q].w += wq * p.w;
            }
        }
    }
#pragma unroll
    for (int off = H; off < 32; off <<= 1) den += __shfl_xor_sync(~0u, den, off);
    float denh[H];
#pragma unroll
    for (int h = 0; h < H; h++) denh[h] = __shfl_sync(~0u, den, h) + 1e-16f;

    const float4* b4 = reinterpret_cast<const float4*>(bias);
    if (EPI == 0) {
        float4* o4 = reinterpret_cast<float4*>(out + (size_t)node * HC);
#pragma unroll
        for (int q = 0; q < Q; q++) {
            float inv = 1.f / denh[hq[q]];
            float4 b = b4[q * 32 + lane];
            float4 v;
            v.x = acc4[q].x * inv + b.x;
            v.y = acc4[q].y * inv + b.y;
            v.z = acc4[q].z * inv + b.z;
            v.w = acc4[q].w * inv + b.w;
            v.x = v.x > 0.f ? v.x : (__expf(v.x) - 1.f);
            v.y = v.y > 0.f ? v.y : (__expf(v.y) - 1.f);
            v.z = v.z > 0.f ? v.z : (__expf(v.z) - 1.f);
            v.w = v.w > 0.f ? v.w : (__expf(v.w) - 1.f);
            o4[q * 32 + lane] = v;
        }
    } else if (EPI == 1) {
        float4* o4 = reinterpret_cast<float4*>(out + (size_t)node * 128);
        float i0 = 1.f / denh[0], i1 = 1.f / denh[H - 1];
        float4 b = b4[lane];
        float4 v;
        v.x = 0.5f * (acc4[0].x * i0 + acc4[1].x * i1) + b.x;
        v.y = 0.5f * (acc4[0].y * i0 + acc4[1].y * i1) + b.y;
        v.z = 0.5f * (acc4[0].z * i0 + acc4[1].z * i1) + b.z;
        v.w = 0.5f * (acc4[0].w * i0 + acc4[1].w * i1) + b.w;
        v.x = v.x > 0.f ? v.x : (__expf(v.x) - 1.f);
        v.y = v.y > 0.f ? v.y : (__expf(v.y) - 1.f);
        v.z = v.z > 0.f ? v.z : (__expf(v.z) - 1.f);
        v.w = v.w > 0.f ? v.w : (__expf(v.w) - 1.f);
        o4[lane] = v;
    } else {
        float4* o4 = reinterpret_cast<float4*>(out + (size_t)node * C);
        float inv = 1.f / denh[0];
        float4 b = b4[lane];
        float4 v;
        v.x = acc4[0].x * inv + b.x;
        v.y = acc4[0].y * inv + b.y;
        v.z = acc4[0].z * inv + b.z;
        v.w = acc4[0].w * inv + b.w;
        o4[lane] = v;
    }
}

// ------------------------------- launch ------------------------------------

extern "C" void kernel_launch(void* const* d_in, const int* in_sizes, int n_in,
                              void* d_out, int out_size) {
    const float* x  = (const float*)d_in[0];
    const void*  ei = d_in[1];
    const float* W1 = (const float*)d_in[2];
    const float* b1 = (const float*)d_in[3];
    const float* W2 = (const float*)d_in[4];
    const float* b2 = (const float*)d_in[5];
    const float* g1_W  = (const float*)d_in[6];
    const float* g1_as = (const float*)d_in[7];
    const float* g1_ad = (const float*)d_in[8];
    const float* g1_b  = (const float*)d_in[9];
    const float* g2_W  = (const float*)d_in[10];
    const float* g2_as = (const float*)d_in[11];
    const float* g2_ad = (const float*)d_in[12];
    const float* g2_b  = (const float*)d_in[13];
    const float* g3_W  = (const float*)d_in[14];
    const float* g3_as = (const float*)d_in[15];
    const float* g3_ad = (const float*)d_in[16];
    const float* g3_b  = (const float*)d_in[17];
    float* out = (float*)d_out;

    int n = in_sizes[0] / 256;
    int e = in_sizes[1] / 2;
    int etot = e + n;

    float *d_h, *d_f, *d_proj;
    cudaGetSymbolAddress((void**)&d_h, g_h);
    cudaGetSymbolAddress((void**)&d_f, g_f);
    cudaGetSymbolAddress((void**)&d_proj, g_proj);

    int nb = (n + 3) / 4;
    int nsb = (n + 1023) / 1024;
    int gy = (n + 127) / 128;

    // --- dtype detect + CSR build ---
    k_detect<<<1, 256>>>((const unsigned int*)ei);
    k_zero_int<<<(n + 255) / 256, 256>>>(n);
    k_count<<<(etot + 255) / 256, 256>>>(ei, e, etot, n);
    k_scan1<<<nsb, 1024>>>(n);
    k_scan2<<<1, 64>>>(nsb, n);
    k_scan3<<<nsb, 1024>>>(n);
    k_scatter<<<(etot + 255) / 256, 256>>>(ei, e, etot, n);

    // --- semantic MLP ---
    k_gemm<1><<<dim3(2, gy), 256>>>(x, W1, b1, d_f, n, 256, 128);
    k_gemm<1><<<dim3(2, gy), 256>>>(d_f, W2, b2, d_h, n, 128, 128);

    // --- GAT1: 128 -> 4 heads x 64, concat -> 256, ELU ---
    k_gemm<0><<<dim3(4, gy), 256>>>(d_h, g1_W, nullptr, d_proj, n, 128, 256);
    k_alpha<4, 64><<<nb, 128>>>(d_proj, g1_as, g1_ad, n);
    k_gather<4><<<(etot + 255) / 256, 256>>>(etot);
    k_agg<4, 64, 0><<<nb, 128>>>(d_proj, g1_b, d_f, n);

    // --- GAT2: 256 -> 2 heads x 128, mean -> 128, ELU ---
    k_gemm<0><<<dim3(4, gy), 256>>>(d_f, g2_W, nullptr, d_proj, n, 256, 256);
    k_alpha<2, 128><<<nb, 128>>>(d_proj, g2_as, g2_ad, n);
    k_gather<2><<<(etot + 255) / 256, 256>>>(etot);
    k_agg<2, 128, 1><<<nb, 128>>>(d_proj, g2_b, d_h, n);

    // --- GAT3: 128 -> 1 head x 128, mean(=id) -> 128 ---
    k_gemm<0><<<dim3(2, gy), 256>>>(d_h, g3_W, nullptr, d_proj, n, 128, 128);
    k_alpha<1, 128><<<nb, 128>>>(d_proj, g3_as, g3_ad, n);
    k_gather<1><<<(etot + 255) / 256, 256>>>(etot);
    k_agg<1, 128, 2><<<nb, 128>>>(d_proj, g3_b, out, n);
}